// round 17
// baseline (speedup 1.0000x reference)
#include <cuda_runtime.h>

// InteractiveGallingModelV6 — v6: two-pass split, both passes widened.
//   Kernel A: serial chain, float4 lanes (512 warps), writes mu + component.
//   Kernel B: parallel plane recompute, 2 float4 items per thread (ILP-2
//             mu loads), 10 STG.128 streaming stores.

#define N_CYCLES 150
#define BATCH    65536
#define QUARTER  (BATCH / 4)            // float4 lanes per step (16384 = 2^14)
#define T_REF    160.0f
#define MU_MIN   0.1f
#define MU_MAX   1.3f

__device__ __forceinline__ float fast_sigmoid(float x) {
    return __fdividef(1.0f, 1.0f + __expf(-x));
}
__device__ __forceinline__ float fast_softplus(float x) {
    return fmaxf(x, 0.0f) + __logf(1.0f + __expf(-fabsf(x)));
}

struct Coef {
    float A, a_mu, a_mu2, C, c_mu, S, s_mu, J, j_mu, v0, v_mu, mu0;
};

__device__ __forceinline__ Coef load_coefs(const float* __restrict__ params,
                                           const float* __restrict__ Tptr)
{
    const float a0       = __ldg(params + 0);
    const float a_T      = __ldg(params + 1);
    const float a_mu     = __ldg(params + 2);
    const float a_mu2    = __ldg(params + 3);
    const float c0       = __ldg(params + 4);
    const float c_mu     = __ldg(params + 5);
    const float c_T      = __ldg(params + 6);
    const float s0       = __ldg(params + 7);
    const float s_mu     = __ldg(params + 8);
    const float s_T      = __ldg(params + 9);
    const float j0       = __ldg(params + 10);
    const float j_mu     = __ldg(params + 11);
    const float j_T      = __ldg(params + 12);
    const float v0       = __ldg(params + 13);
    const float v_mu     = __ldg(params + 14);
    const float mu0_base = __ldg(params + 15);
    const float mu0_T    = __ldg(params + 16);
    const float dT = __ldg(Tptr) - T_REF;

    Coef k;
    k.A = a0 + a_T * dT;  k.a_mu = a_mu;  k.a_mu2 = a_mu2;
    k.C = c0 + c_T * dT;  k.c_mu = c_mu;
    k.S = s0 + s_T * dT;  k.s_mu = s_mu;
    k.J = j0 + j_T * dT;  k.j_mu = j_mu;
    k.v0 = v0;            k.v_mu = v_mu;
    k.mu0 = fminf(fmaxf(mu0_base + mu0_T * dT, MU_MIN), MU_MAX);
    return k;
}

// ─────────────────────────── Kernel A: the chain ──────────────────────────
__global__ void __launch_bounds__(128)
galling_chain_kernel(const float* __restrict__ params,
                     const float* __restrict__ Tptr,
                     const float* __restrict__ u,
                     const float* __restrict__ noise,
                     float* __restrict__ out)
{
    const int b = blockIdx.x * blockDim.x + threadIdx.x;   // float4 lane

    const Coef k = load_coefs(params, Tptr);

    float mu[4] = {k.mu0, k.mu0, k.mu0, k.mu0};

    const float4* __restrict__ up = (const float4*)u     + b;
    const float4* __restrict__ np = (const float4*)noise + b;

    float4* __restrict__ o0 = (float4*)out + b;                 // mu
    float4* __restrict__ o1 = o0 + N_CYCLES * QUARTER;          // component

    // depth-2 prefetch (R12: deeper does not help)
    float4 ub[2], nb[2];
    ub[0] = __ldcs(up);            nb[0] = __ldcs(np);
    ub[1] = __ldcs(up + QUARTER);  nb[1] = __ldcs(np + QUARTER);

    #pragma unroll 2
    for (int t = 0; t < N_CYCLES; ++t) {
        const int slot = t & 1;
        const float4 uc = ub[slot];
        const float4 nc = nb[slot];
        if (t + 2 < N_CYCLES) {
            const int off = (t + 2) * QUARTER;
            ub[slot] = __ldcs(up + off);
            nb[slot] = __ldcs(np + off);
        }

        const float uu[4] = {uc.x, uc.y, uc.z, uc.w};
        const float nn[4] = {nc.x, nc.y, nc.z, nc.w};
        float comp[4];

        #pragma unroll
        for (int i = 0; i < 4; ++i) {
            const float m  = mu[i];
            const float pi = fast_sigmoid(fmaf(m, fmaf(m, k.a_mu2, k.a_mu), k.A));
            const bool  st = uu[i] < pi;
            const float dmu = st
                ? fmaf(fast_softplus(fmaf(m, k.s_mu, k.S)), nn[i], fmaf(m, k.c_mu, k.C))
                : fmaf(fast_softplus(fmaf(m, k.v_mu, k.v0)), nn[i], fmaf(m, k.j_mu, k.J));
            comp[i] = st ? 0.0f : 1.0f;
            mu[i] = fminf(fmaxf(m + dmu, MU_MIN), MU_MAX);
        }

        const int idx = t * QUARTER;
        o0[idx] = make_float4(mu[0], mu[1], mu[2], mu[3]);     // keep in L2 for B
        __stcs(o1 + idx, make_float4(comp[0], comp[1], comp[2], comp[3]));
    }
}

// ─────────────────── Kernel B: parallel plane recompute ───────────────────
// Each thread processes TWO adjacent float4 items (ILP-2 on the mu load).
__global__ void __launch_bounds__(256)
galling_planes_kernel(const float* __restrict__ params,
                      const float* __restrict__ Tptr,
                      float* __restrict__ out)
{
    const int pair = blockIdx.x * blockDim.x + threadIdx.x;   // float4 pair
    const int idx  = pair * 2;
    const int t    = idx >> 14;                // QUARTER == 2^14
    const int b4   = idx & (QUARTER - 1);      // pair stays within one t

    const Coef k = load_coefs(params, Tptr);

    // mu at step entry = mu[t-1] (plane 0, written by A — mostly L2 hits)
    float4 m0, m1;
    if (t == 0) {
        m0 = make_float4(k.mu0, k.mu0, k.mu0, k.mu0);
        m1 = m0;
    } else {
        const float4* mu_src = (const float4*)out + (t - 1) * QUARTER + b4;
        m0 = __ldg(mu_src);         // both loads issued back-to-back: MLP 2
        m1 = __ldg(mu_src + 1);
    }

    float pi[8], d1[8], s1[8], d2[8], s2[8];
    const float m[8] = {m0.x, m0.y, m0.z, m0.w, m1.x, m1.y, m1.z, m1.w};
    #pragma unroll
    for (int i = 0; i < 8; ++i) {
        const float mu = m[i];
        pi[i] = fast_sigmoid(fmaf(mu, fmaf(mu, k.a_mu2, k.a_mu), k.A));
        d1[i] = fmaf(mu, k.c_mu, k.C);
        s1[i] = fast_softplus(fmaf(mu, k.s_mu, k.S));
        d2[i] = fmaf(mu, k.j_mu, k.J);
        s2[i] = fast_softplus(fmaf(mu, k.v_mu, k.v0));
    }

    const int NB4  = N_CYCLES * QUARTER;        // float4 per plane
    const int base = t * QUARTER + b4;
    float4* o = (float4*)out;
    __stcs(o + 2 * NB4 + base,     make_float4(pi[0], pi[1], pi[2], pi[3]));
    __stcs(o + 2 * NB4 + base + 1, make_float4(pi[4], pi[5], pi[6], pi[7]));
    __stcs(o + 3 * NB4 + base,     make_float4(d1[0], d1[1], d1[2], d1[3]));
    __stcs(o + 3 * NB4 + base + 1, make_float4(d1[4], d1[5], d1[6], d1[7]));
    __stcs(o + 4 * NB4 + base,     make_float4(s1[0], s1[1], s1[2], s1[3]));
    __stcs(o + 4 * NB4 + base + 1, make_float4(s1[4], s1[5], s1[6], s1[7]));
    __stcs(o + 5 * NB4 + base,     make_float4(d2[0], d2[1], d2[2], d2[3]));
    __stcs(o + 5 * NB4 + base + 1, make_float4(d2[4], d2[5], d2[6], d2[7]));
    __stcs(o + 6 * NB4 + base,     make_float4(s2[0], s2[1], s2[2], s2[3]));
    __stcs(o + 6 * NB4 + base + 1, make_float4(s2[4], s2[5], s2[6], s2[7]));
}

extern "C" void kernel_launch(void* const* d_in, const int* in_sizes, int n_in,
                              void* d_out, int out_size)
{
    const float* params = (const float*)d_in[0];
    const float* T      = (const float*)d_in[1];
    const float* u      = (const float*)d_in[2];
    const float* noise  = (const float*)d_in[3];
    float* out          = (float*)d_out;

    // A: 16384 float4 lanes / 128 thr = 128 CTAs (512 warps)
    galling_chain_kernel<<<QUARTER / 128, 128>>>(params, T, u, noise, out);

    // B: 150*16384/2 = 1,228,800 pairs / 256 thr = 4800 CTAs
    galling_planes_kernel<<<(N_CYCLES * QUARTER / 2) / 256, 256>>>(params, T, out);
}